// round 2
// baseline (speedup 1.0000x reference)
#include <cuda_runtime.h>
#include <math.h>

#define FULL 0xffffffffu
#define D 64
#define HID 32
#define TRAJ_LEN 11
#define MAX_INNER 64

// Tsit5 tableau
#define A21f 0.161f
#define A31f -0.008480655492356989f
#define A32f 0.335480655492357f
#define A41f 2.8971530571054935f
#define A42f -6.359448489975075f
#define A43f 4.3622954328695815f
#define A51f 5.325864828439257f
#define A52f -11.748883564062828f
#define A53f 7.4955393428898365f
#define A54f -0.09249506636175525f
#define A61f 5.86145544294642f
#define A62f -12.92096931784711f
#define A63f 8.159367898576159f
#define A64f -0.071584973281401f
#define A65f -0.028269050394068383f
#define B1f 0.09646076681806523f
#define B2f 0.01f
#define B3f 0.4798896504144996f
#define B4f 1.379008574103742f
#define B5f -3.290069515436081f
#define B6f 2.324710524099774f
#define E1f -0.00178001105222577714f
#define E2f -0.0008164344596567469f
#define E3f 0.007880878010261995f
#define E4f -0.1447110071732629f
#define E5f 0.5823571654525552f
#define E6f -0.45808210592918697f
#define E7f 0.015151515151515152f

__device__ __forceinline__ float softplus_f(float x) {
    // jax.nn.softplus = max(x,0) + log1p(exp(-|x|))
    return fmaxf(x, 0.0f) + log1pf(expf(-fabsf(x)));
}

// One warp evaluates the MLP for one trajectory.
// Lane i holds input components (i, i+32); outputs components (i, i+32).
// Weights are transposed in shared memory for conflict-free lane access.
__device__ __forceinline__ void mlp_eval(
    const float* __restrict__ sW1,   // [64][32]  (input j, hidden i)
    const float* __restrict__ sW2,   // [32][32]  (input j, hidden i)
    const float* __restrict__ sW3,   // [32][64]  (hidden j, output d)
    const float* __restrict__ sb1,
    const float* __restrict__ sb2,
    const float* __restrict__ sb3,
    int lane, float ya, float yb, float& oa, float& ob)
{
    // layer 1: h1[i] = softplus(b1[i] + sum_j W1[i][j] * y[j])
    float acc0 = sb1[lane];
    float acc1 = 0.0f;
    #pragma unroll
    for (int j = 0; j < 32; j++) {
        float a0 = __shfl_sync(FULL, ya, j);
        float a1 = __shfl_sync(FULL, yb, j);
        acc0 = fmaf(sW1[j * 32 + lane], a0, acc0);
        acc1 = fmaf(sW1[(j + 32) * 32 + lane], a1, acc1);
    }
    float h1 = softplus_f(acc0 + acc1);

    // layer 2
    float c0 = sb2[lane];
    float c1 = 0.0f;
    #pragma unroll
    for (int j = 0; j < 16; j++) {
        float u0 = __shfl_sync(FULL, h1, 2 * j);
        float u1 = __shfl_sync(FULL, h1, 2 * j + 1);
        c0 = fmaf(sW2[(2 * j) * 32 + lane], u0, c0);
        c1 = fmaf(sW2[(2 * j + 1) * 32 + lane], u1, c1);
    }
    float h2 = softplus_f(c0 + c1);

    // layer 3: out[d] = b3[d] + sum_j W3[d][j] * h2[j]; lane does d=lane, lane+32
    float o0 = sb3[lane];
    float o1 = sb3[lane + 32];
    #pragma unroll
    for (int j = 0; j < 32; j++) {
        float hj = __shfl_sync(FULL, h2, j);
        o0 = fmaf(sW3[j * 64 + lane], hj, o0);
        o1 = fmaf(sW3[j * 64 + lane + 32], hj, o1);
    }
    oa = o0;
    ob = o1;
}

__global__ void __launch_bounds__(256)
ode_tsit5_kernel(
    const float* __restrict__ x0,
    const float* __restrict__ W1, const float* __restrict__ b1,
    const float* __restrict__ W2, const float* __restrict__ b2,
    const float* __restrict__ W3, const float* __restrict__ b3,
    const int* __restrict__ Tp,
    float* __restrict__ out, int nb, int out_size)
{
    __shared__ float sW1[D * HID];    // transposed [64][32]
    __shared__ float sW2[HID * HID];  // transposed [32][32]
    __shared__ float sW3[HID * D];    // transposed [32][64]
    __shared__ float sb1[HID], sb2[HID], sb3[D];

    int tid = threadIdx.x;
    for (int idx = tid; idx < HID * D; idx += blockDim.x) {
        int i = idx / D, j = idx % D;          // W1[i][j], i<32, j<64
        sW1[j * HID + i] = W1[idx];
    }
    for (int idx = tid; idx < HID * HID; idx += blockDim.x) {
        int i = idx / HID, j = idx % HID;
        sW2[j * HID + i] = W2[idx];
    }
    for (int idx = tid; idx < D * HID; idx += blockDim.x) {
        int dd = idx / HID, j = idx % HID;     // W3[d][j], d<64, j<32
        sW3[j * D + dd] = W3[idx];
    }
    if (tid < HID) { sb1[tid] = b1[tid]; sb2[tid] = b2[tid]; }
    if (tid < D)   { sb3[tid] = b3[tid]; }
    __syncthreads();

    int gwarp = (int)((blockIdx.x * blockDim.x + tid) >> 5);
    int lane = tid & 31;
    if (gwarp >= nb) return;

    // T may arrive as int32 or float32 bits; 10-as-float-bits is a huge int,
    // 10-as-int-bits is a denormal float — disambiguate heuristically.
    int ti = *Tp;
    float Tf = (ti > 0 && ti < 1000000) ? (float)ti : __int_as_float(ti);
    float tstep = Tf / (float)(TRAJ_LEN - 1);

    float ya = x0[(size_t)gwarp * D + lane];
    float yb = x0[(size_t)gwarp * D + lane + HID];

    size_t obase = (size_t)gwarp * TRAJ_LEN * D;
    out[obase + lane] = ya;
    out[obase + lane + HID] = yb;

    float t = 0.0f;
    float dt = 1e-3f;
    int n = 0;

    // FSAL-style k1 cache: k1 = f(y). After an accepted step, f(y_new) == k7
    // bitwise; after a rejected step, y unchanged so k1 unchanged. Exact.
    float k1a, k1b;
    mlp_eval(sW1, sW2, sW3, sb1, sb2, sb3, lane, ya, yb, k1a, k1b);

    for (int s = 1; s < TRAJ_LEN; s++) {
        float tt = tstep * (float)s;
        for (int it = 0; it < MAX_INNER; it++) {
            float remaining = tt - t;
            if (remaining <= 1e-12f) break;   // masked iterations leave state unchanged
            float h = fminf(dt, fmaxf(remaining, 0.0f));

            float k2a, k2b, k3a, k3b, k4a, k4b, k5a, k5b, k6a, k6b, k7a, k7b;
            float za, zb;

            za = fmaf(h, A21f * k1a, ya);
            zb = fmaf(h, A21f * k1b, yb);
            mlp_eval(sW1, sW2, sW3, sb1, sb2, sb3, lane, za, zb, k2a, k2b);

            za = fmaf(h, fmaf(A32f, k2a, A31f * k1a), ya);
            zb = fmaf(h, fmaf(A32f, k2b, A31f * k1b), yb);
            mlp_eval(sW1, sW2, sW3, sb1, sb2, sb3, lane, za, zb, k3a, k3b);

            za = fmaf(h, fmaf(A43f, k3a, fmaf(A42f, k2a, A41f * k1a)), ya);
            zb = fmaf(h, fmaf(A43f, k3b, fmaf(A42f, k2b, A41f * k1b)), yb);
            mlp_eval(sW1, sW2, sW3, sb1, sb2, sb3, lane, za, zb, k4a, k4b);

            za = fmaf(h, fmaf(A54f, k4a, fmaf(A53f, k3a, fmaf(A52f, k2a, A51f * k1a))), ya);
            zb = fmaf(h, fmaf(A54f, k4b, fmaf(A53f, k3b, fmaf(A52f, k2b, A51f * k1b))), yb);
            mlp_eval(sW1, sW2, sW3, sb1, sb2, sb3, lane, za, zb, k5a, k5b);

            za = fmaf(h, fmaf(A65f, k5a, fmaf(A64f, k4a, fmaf(A63f, k3a, fmaf(A62f, k2a, A61f * k1a)))), ya);
            zb = fmaf(h, fmaf(A65f, k5b, fmaf(A64f, k4b, fmaf(A63f, k3b, fmaf(A62f, k2b, A61f * k1b)))), yb);
            mlp_eval(sW1, sW2, sW3, sb1, sb2, sb3, lane, za, zb, k6a, k6b);

            float y5a = fmaf(h, fmaf(B6f, k6a, fmaf(B5f, k5a, fmaf(B4f, k4a, fmaf(B3f, k3a, fmaf(B2f, k2a, B1f * k1a))))), ya);
            float y5b = fmaf(h, fmaf(B6f, k6b, fmaf(B5f, k5b, fmaf(B4f, k4b, fmaf(B3f, k3b, fmaf(B2f, k2b, B1f * k1b))))), yb);

            mlp_eval(sW1, sW2, sW3, sb1, sb2, sb3, lane, y5a, y5b, k7a, k7b);

            float erra = h * fmaf(E7f, k7a, fmaf(E6f, k6a, fmaf(E5f, k5a, fmaf(E4f, k4a, fmaf(E3f, k3a, fmaf(E2f, k2a, E1f * k1a))))));
            float errb = h * fmaf(E7f, k7b, fmaf(E6f, k6b, fmaf(E5f, k5b, fmaf(E4f, k4b, fmaf(E3f, k3b, fmaf(E2f, k2b, E1f * k1b))))));

            float sca = fmaf(1e-3f, fmaxf(fabsf(ya), fabsf(y5a)), 1e-6f);
            float scb = fmaf(1e-3f, fmaxf(fabsf(yb), fabsf(y5b)), 1e-6f);
            float e0 = erra / sca;
            float e1 = errb / scb;
            float ss = fmaf(e0, e0, e1 * e1);
            #pragma unroll
            for (int off = 16; off > 0; off >>= 1)
                ss += __shfl_xor_sync(FULL, ss, off);
            float enorm = fmaxf(sqrtf(ss * (1.0f / 64.0f)), 1e-10f);

            bool accept = (enorm <= 1.0f);
            float fac = fminf(fmaxf(0.9f * powf(enorm, -0.2f), 0.1f), 5.0f);

            if (accept) {
                t = t + h;
                ya = y5a; yb = y5b;
                k1a = k7a; k1b = k7b;   // FSAL: f(y_new) == k7 bitwise
            }
            dt = fmaxf(h * fac, 1e-8f);
            n++;
        }
        out[obase + (size_t)s * D + lane] = ya;
        out[obase + (size_t)s * D + lane + HID] = yb;
    }

    // second output: sum of attempt counts (integer-exact in f32, order-free)
    int traj_elems = nb * TRAJ_LEN * D;
    if (lane == 0 && out_size > traj_elems) {
        atomicAdd(&out[traj_elems], (float)n);
    }
}

extern "C" void kernel_launch(void* const* d_in, const int* in_sizes, int n_in,
                              void* d_out, int out_size) {
    const float* x0 = (const float*)d_in[0];
    const float* W1 = (const float*)d_in[1];
    const float* b1 = (const float*)d_in[2];
    const float* W2 = (const float*)d_in[3];
    const float* b2 = (const float*)d_in[4];
    const float* W3 = (const float*)d_in[5];
    const float* b3 = (const float*)d_in[6];
    const int*   Tp = (const int*)d_in[7];
    float* out = (float*)d_out;

    int nb = in_sizes[0] / D;                 // 4096 trajectories
    int traj_elems = nb * TRAJ_LEN * D;

    if (out_size > traj_elems) {
        // zero the scalar tail (step-count accumulator) before the kernel
        cudaMemsetAsync((char*)d_out + (size_t)traj_elems * sizeof(float), 0,
                        (size_t)(out_size - traj_elems) * sizeof(float), 0);
    }

    const int threads = 256;                   // 8 warps = 8 trajectories / block
    int blocks = (nb * 32 + threads - 1) / threads;
    ode_tsit5_kernel<<<blocks, threads>>>(x0, W1, b1, W2, b2, W3, b3, Tp,
                                          out, nb, out_size);
}

// round 5
// speedup vs baseline: 1.0946x; 1.0946x over previous
#include <cuda_runtime.h>
#include <math.h>

#define FULL 0xffffffffu
#define D 64
#define HID 32
#define TRAJ_LEN 11
#define MAX_INNER 64

// Tsit5 tableau
#define A21f 0.161f
#define A31f -0.008480655492356989f
#define A32f 0.335480655492357f
#define A41f 2.8971530571054935f
#define A42f -6.359448489975075f
#define A43f 4.3622954328695815f
#define A51f 5.325864828439257f
#define A52f -11.748883564062828f
#define A53f 7.4955393428898365f
#define A54f -0.09249506636175525f
#define A61f 5.86145544294642f
#define A62f -12.92096931784711f
#define A63f 8.159367898576159f
#define A64f -0.071584973281401f
#define A65f -0.028269050394068383f
#define B1f 0.09646076681806523f
#define B2f 0.01f
#define B3f 0.4798896504144996f
#define B4f 1.379008574103742f
#define B5f -3.290069515436081f
#define B6f 2.324710524099774f
#define E1f -0.00178001105222577714f
#define E2f -0.0008164344596567469f
#define E3f 0.007880878010261995f
#define E4f -0.1447110071732629f
#define E5f 0.5823571654525552f
#define E6f -0.45808210592918697f
#define E7f 0.015151515151515152f

__device__ __forceinline__ float softplus_f(float x) {
    // softplus = max(x,0) + log1p(exp(-|x|)); fast MUFU version.
    float e = __expf(-fabsf(x));
    return fmaxf(x, 0.0f) + __logf(1.0f + e);
}

// Quad-j interleaved weight layouts (all LDS.128, lane-consecutive -> conflict-free):
//   sW1q[q][i][r] = W1[i][4q+r]   q<16, i<32   (float4 per (q,i))
//   sW2q[q][i][r] = W2[i][4q+r]   q<8,  i<32
//   sW3q[q][d][r] = W3[d][4q+r]   q<8,  d<64
__device__ __forceinline__ void mlp_eval(
    const float4* __restrict__ w1,   // [16][32]
    const float4* __restrict__ w2,   // [8][32]
    const float4* __restrict__ w3,   // [8][64]
    float bias1, float bias2, float bias3a, float bias3b,
    int lane, float ya, float yb, float& oa, float& ob)
{
    // ---- layer 1: h1[lane] = softplus(b1 + sum_{j<64} W1[lane][j] y[j])
    float a0 = 0.f, a1 = 0.f, a2 = 0.f, a3 = 0.f;
    #pragma unroll
    for (int q = 0; q < 8; q++) {
        float4 w = w1[q * 32 + lane];
        a0 = fmaf(w.x, __shfl_sync(FULL, ya, 4 * q + 0), a0);
        a1 = fmaf(w.y, __shfl_sync(FULL, ya, 4 * q + 1), a1);
        a2 = fmaf(w.z, __shfl_sync(FULL, ya, 4 * q + 2), a2);
        a3 = fmaf(w.w, __shfl_sync(FULL, ya, 4 * q + 3), a3);
    }
    #pragma unroll
    for (int q = 8; q < 16; q++) {
        float4 w = w1[q * 32 + lane];
        a0 = fmaf(w.x, __shfl_sync(FULL, yb, 4 * (q - 8) + 0), a0);
        a1 = fmaf(w.y, __shfl_sync(FULL, yb, 4 * (q - 8) + 1), a1);
        a2 = fmaf(w.z, __shfl_sync(FULL, yb, 4 * (q - 8) + 2), a2);
        a3 = fmaf(w.w, __shfl_sync(FULL, yb, 4 * (q - 8) + 3), a3);
    }
    float h1 = softplus_f(((a0 + a1) + (a2 + a3)) + bias1);

    // ---- layer 2
    float c0 = 0.f, c1 = 0.f, c2 = 0.f, c3 = 0.f;
    #pragma unroll
    for (int q = 0; q < 8; q++) {
        float4 w = w2[q * 32 + lane];
        c0 = fmaf(w.x, __shfl_sync(FULL, h1, 4 * q + 0), c0);
        c1 = fmaf(w.y, __shfl_sync(FULL, h1, 4 * q + 1), c1);
        c2 = fmaf(w.z, __shfl_sync(FULL, h1, 4 * q + 2), c2);
        c3 = fmaf(w.w, __shfl_sync(FULL, h1, 4 * q + 3), c3);
    }
    float h2 = softplus_f(((c0 + c1) + (c2 + c3)) + bias2);

    // ---- layer 3: out[d] for d = lane, lane+32
    float o0 = 0.f, o1 = 0.f, o2 = 0.f, o3 = 0.f;
    float p0 = 0.f, p1 = 0.f, p2 = 0.f, p3 = 0.f;
    #pragma unroll
    for (int q = 0; q < 8; q++) {
        float4 wA = w3[q * 64 + lane];
        float4 wB = w3[q * 64 + lane + 32];
        float h0 = __shfl_sync(FULL, h2, 4 * q + 0);
        float hh1 = __shfl_sync(FULL, h2, 4 * q + 1);
        float hh2 = __shfl_sync(FULL, h2, 4 * q + 2);
        float hh3 = __shfl_sync(FULL, h2, 4 * q + 3);
        o0 = fmaf(wA.x, h0, o0);  p0 = fmaf(wB.x, h0, p0);
        o1 = fmaf(wA.y, hh1, o1); p1 = fmaf(wB.y, hh1, p1);
        o2 = fmaf(wA.z, hh2, o2); p2 = fmaf(wB.z, hh2, p2);
        o3 = fmaf(wA.w, hh3, o3); p3 = fmaf(wB.w, hh3, p3);
    }
    oa = ((o0 + o1) + (o2 + o3)) + bias3a;
    ob = ((p0 + p1) + (p2 + p3)) + bias3b;
}

__global__ void __launch_bounds__(256)
ode_tsit5_kernel(
    const float* __restrict__ x0,
    const float* __restrict__ W1, const float* __restrict__ b1,
    const float* __restrict__ W2, const float* __restrict__ b2,
    const float* __restrict__ W3, const float* __restrict__ b3,
    const int* __restrict__ Tp,
    float* __restrict__ out, int nb, int out_size)
{
    __shared__ float4 sW1q[16 * 32];
    __shared__ float4 sW2q[8 * 32];
    __shared__ float4 sW3q[8 * 64];

    int tid = threadIdx.x;
    // sW1q[q*32 + i] = W1[i][4q .. 4q+3],  W1 row-major [32][64]
    for (int idx = tid; idx < 16 * 32; idx += blockDim.x) {
        int q = idx >> 5, i = idx & 31;
        const float* src = W1 + i * 64 + 4 * q;
        sW1q[idx] = make_float4(src[0], src[1], src[2], src[3]);
    }
    // sW2q[q*32 + i] = W2[i][4q .. 4q+3],  W2 [32][32]
    for (int idx = tid; idx < 8 * 32; idx += blockDim.x) {
        int q = idx >> 5, i = idx & 31;
        const float* src = W2 + i * 32 + 4 * q;
        sW2q[idx] = make_float4(src[0], src[1], src[2], src[3]);
    }
    // sW3q[q*64 + d] = W3[d][4q .. 4q+3],  W3 [64][32]
    for (int idx = tid; idx < 8 * 64; idx += blockDim.x) {
        int q = idx >> 6, dd = idx & 63;
        const float* src = W3 + dd * 32 + 4 * q;
        sW3q[idx] = make_float4(src[0], src[1], src[2], src[3]);
    }
    __syncthreads();

    int gwarp = (int)((blockIdx.x * blockDim.x + tid) >> 5);
    int lane = tid & 31;
    if (gwarp >= nb) return;

    // biases are lane-constant for the whole run -> registers
    float bias1 = b1[lane];
    float bias2 = b2[lane];
    float bias3a = b3[lane];
    float bias3b = b3[lane + 32];

    // T may arrive as int32 or float32 bits; disambiguate heuristically.
    int ti = *Tp;
    float Tf = (ti > 0 && ti < 1000000) ? (float)ti : __int_as_float(ti);
    float tstep = Tf / (float)(TRAJ_LEN - 1);

    float ya = x0[(size_t)gwarp * D + lane];
    float yb = x0[(size_t)gwarp * D + lane + HID];

    size_t obase = (size_t)gwarp * TRAJ_LEN * D;
    out[obase + lane] = ya;
    out[obase + lane + HID] = yb;

    float t = 0.0f;
    float dt = 1e-3f;
    int n = 0;

    // FSAL k1 cache: exact (accepted step -> f(y_new)==k7 bitwise; rejected -> y unchanged)
    float k1a, k1b;
    mlp_eval(sW1q, sW2q, sW3q, bias1, bias2, bias3a, bias3b, lane, ya, yb, k1a, k1b);

    for (int s = 1; s < TRAJ_LEN; s++) {
        float tt = tstep * (float)s;
        for (int it = 0; it < MAX_INNER; it++) {
            float remaining = tt - t;
            if (remaining <= 1e-12f) break;   // masked iterations leave state unchanged
            float h = fminf(dt, fmaxf(remaining, 0.0f));

            float k2a, k2b, k3a, k3b, k4a, k4b, k5a, k5b, k6a, k6b, k7a, k7b;
            float za, zb;

            za = fmaf(h, A21f * k1a, ya);
            zb = fmaf(h, A21f * k1b, yb);
            mlp_eval(sW1q, sW2q, sW3q, bias1, bias2, bias3a, bias3b, lane, za, zb, k2a, k2b);

            za = fmaf(h, fmaf(A32f, k2a, A31f * k1a), ya);
            zb = fmaf(h, fmaf(A32f, k2b, A31f * k1b), yb);
            mlp_eval(sW1q, sW2q, sW3q, bias1, bias2, bias3a, bias3b, lane, za, zb, k3a, k3b);

            za = fmaf(h, fmaf(A43f, k3a, fmaf(A42f, k2a, A41f * k1a)), ya);
            zb = fmaf(h, fmaf(A43f, k3b, fmaf(A42f, k2b, A41f * k1b)), yb);
            mlp_eval(sW1q, sW2q, sW3q, bias1, bias2, bias3a, bias3b, lane, za, zb, k4a, k4b);

            za = fmaf(h, fmaf(A54f, k4a, fmaf(A53f, k3a, fmaf(A52f, k2a, A51f * k1a))), ya);
            zb = fmaf(h, fmaf(A54f, k4b, fmaf(A53f, k3b, fmaf(A52f, k2b, A51f * k1b))), yb);
            mlp_eval(sW1q, sW2q, sW3q, bias1, bias2, bias3a, bias3b, lane, za, zb, k5a, k5b);

            za = fmaf(h, fmaf(A65f, k5a, fmaf(A64f, k4a, fmaf(A63f, k3a, fmaf(A62f, k2a, A61f * k1a)))), ya);
            zb = fmaf(h, fmaf(A65f, k5b, fmaf(A64f, k4b, fmaf(A63f, k3b, fmaf(A62f, k2b, A61f * k1b)))), yb);
            mlp_eval(sW1q, sW2q, sW3q, bias1, bias2, bias3a, bias3b, lane, za, zb, k6a, k6b);

            float y5a = fmaf(h, fmaf(B6f, k6a, fmaf(B5f, k5a, fmaf(B4f, k4a, fmaf(B3f, k3a, fmaf(B2f, k2a, B1f * k1a))))), ya);
            float y5b = fmaf(h, fmaf(B6f, k6b, fmaf(B5f, k5b, fmaf(B4f, k4b, fmaf(B3f, k3b, fmaf(B2f, k2b, B1f * k1b))))), yb);

            mlp_eval(sW1q, sW2q, sW3q, bias1, bias2, bias3a, bias3b, lane, y5a, y5b, k7a, k7b);

            float erra = h * fmaf(E7f, k7a, fmaf(E6f, k6a, fmaf(E5f, k5a, fmaf(E4f, k4a, fmaf(E3f, k3a, fmaf(E2f, k2a, E1f * k1a))))));
            float errb = h * fmaf(E7f, k7b, fmaf(E6f, k6b, fmaf(E5f, k5b, fmaf(E4f, k4b, fmaf(E3f, k3b, fmaf(E2f, k2b, E1f * k1b))))));

            float sca = fmaf(1e-3f, fmaxf(fabsf(ya), fabsf(y5a)), 1e-6f);
            float scb = fmaf(1e-3f, fmaxf(fabsf(yb), fabsf(y5b)), 1e-6f);
            float e0 = erra / sca;
            float e1 = errb / scb;
            float ss = fmaf(e0, e0, e1 * e1);
            #pragma unroll
            for (int off = 16; off > 0; off >>= 1)
                ss += __shfl_xor_sync(FULL, ss, off);
            float enorm = fmaxf(sqrtf(ss * (1.0f / 64.0f)), 1e-10f);

            bool accept = (enorm <= 1.0f);
            float fac = fminf(fmaxf(0.9f * __powf(enorm, -0.2f), 0.1f), 5.0f);

            if (accept) {
                t = t + h;
                ya = y5a; yb = y5b;
                k1a = k7a; k1b = k7b;   // FSAL
            }
            dt = fmaxf(h * fac, 1e-8f);
            n++;
        }
        out[obase + (size_t)s * D + lane] = ya;
        out[obase + (size_t)s * D + lane + HID] = yb;
    }

    // second output: sum of attempt counts (integer-exact in f32, order-free)
    int traj_elems = nb * TRAJ_LEN * D;
    if (lane == 0 && out_size > traj_elems) {
        atomicAdd(&out[traj_elems], (float)n);
    }
}

extern "C" void kernel_launch(void* const* d_in, const int* in_sizes, int n_in,
                              void* d_out, int out_size) {
    const float* x0 = (const float*)d_in[0];
    const float* W1 = (const float*)d_in[1];
    const float* b1 = (const float*)d_in[2];
    const float* W2 = (const float*)d_in[3];
    const float* b2 = (const float*)d_in[4];
    const float* W3 = (const float*)d_in[5];
    const float* b3 = (const float*)d_in[6];
    const int*   Tp = (const int*)d_in[7];
    float* out = (float*)d_out;

    int nb = in_sizes[0] / D;                 // 4096 trajectories
    int traj_elems = nb * TRAJ_LEN * D;

    if (out_size > traj_elems) {
        cudaMemsetAsync((char*)d_out + (size_t)traj_elems * sizeof(float), 0,
                        (size_t)(out_size - traj_elems) * sizeof(float), 0);
    }

    const int threads = 256;                   // 8 warps = 8 trajectories / block
    int blocks = (nb * 32 + threads - 1) / threads;
    ode_tsit5_kernel<<<blocks, threads>>>(x0, W1, b1, W2, b2, W3, b3, Tp,
                                          out, nb, out_size);
}